// round 1
// baseline (speedup 1.0000x reference)
#include <cuda_runtime.h>
#include <stdint.h>

#define BATCH 64
#define T 2048
#define HID 256
#define FAST 64
#define SLOW 256
#define VOCAB 64
#define TLOOP (T - 3)

// Inter-kernel scratch (static device globals: allowed, no allocation)
__device__ unsigned long long g_act_mask;
__device__ int g_rank_of_vid[VOCAB];
__device__ int g_vid_of_rank[VOCAB];
__device__ float g_EWo[VOCAB * VOCAB];   // [v][j] = emb[v] @ Wo

// ---------------------------------------------------------------------------
// Kernel A: per-vocab precompute. act[v], dem-rank[v], EWo = emb @ Wo
// ---------------------------------------------------------------------------
__global__ void prep_kernel(const float* __restrict__ emb,
                            const float* __restrict__ Wg,
                            const float* __restrict__ bg,
                            const float* __restrict__ Wd,
                            const float* __restrict__ bd,
                            const float* __restrict__ Wo) {
    __shared__ float s_dem[VOCAB];
    __shared__ unsigned int s_ball[2];
    int tid = threadIdx.x;

    if (tid < VOCAB) {
        const float* er = emb + tid * HID;
        float gd = 0.f, dd = 0.f;
        #pragma unroll 8
        for (int h = 0; h < HID; ++h) {
            float e = er[h];
            gd += e * Wg[h];
            dd += e * Wd[h];
        }
        float x = gd + bg[0];
        float ws = 1.f / (1.f + expf(-x));
        s_dem[tid] = dd + bd[0];
        unsigned act = (ws >= 0.4f) ? 1u : 0u;
        unsigned bal = __ballot_sync(0xffffffffu, act != 0u);
        if ((tid & 31) == 0) s_ball[tid >> 5] = bal;
    }
    __syncthreads();
    if (tid == 0) {
        g_act_mask = (unsigned long long)s_ball[0] |
                     ((unsigned long long)s_ball[1] << 32);
    }
    if (tid < VOCAB) {
        // stable rank by ascending dem (tie: lower vid first)
        float dv = s_dem[tid];
        int rank = 0;
        for (int u = 0; u < VOCAB; ++u) {
            float du = s_dem[u];
            if (du < dv || (du == dv && u < tid)) rank++;
        }
        g_rank_of_vid[tid] = rank;
        g_vid_of_rank[rank] = tid;
    }
    // EWo[v][j] = sum_h emb[v][h] * Wo[h][j]
    for (int idx = tid; idx < VOCAB * VOCAB; idx += blockDim.x) {
        int v = idx >> 6, j = idx & 63;
        const float* er = emb + v * HID;
        float acc = 0.f;
        #pragma unroll 8
        for (int h = 0; h < HID; ++h) acc += er[h] * Wo[h * VOCAB + j];
        g_EWo[idx] = acc;
    }
}

// ---------------------------------------------------------------------------
// Kernel B: one block per batch.
//   phase 1: warp 0 compacts active token ranks (order-preserving)
//   phase 2: thread 0 runs the O(1)/step tiered-memory automaton
//   phase 3: fused read-head (q matvec, softmax over occupied slots, logits)
// ---------------------------------------------------------------------------
__global__ void __launch_bounds__(128) main_kernel(
    const int* __restrict__ seq,
    const float* __restrict__ emb,
    const float* __restrict__ Wq,
    const float* __restrict__ bq,
    const float* __restrict__ bo,
    float* __restrict__ out) {

    __shared__ __align__(8) uint8_t s_list[2048];  // compacted active ranks
    __shared__ unsigned long long s_slot[FAST];    // per-rank slot bitmask
    __shared__ uint8_t s_fast[FAST];               // rank held by fast slot i
    __shared__ uint8_t s_slow[SLOW];               // rank held by slow slot j
    __shared__ int s_rankv[VOCAB];                 // vid -> rank
    __shared__ int s_vid[VOCAB];                   // rank -> vid
    __shared__ int s_nact, s_fcnt, s_swrites;
    __shared__ float s_q[HID];
    __shared__ float s_p[VOCAB];                   // score per rank
    __shared__ float s_wv[VOCAB];                  // attn weight per vid
    __shared__ float s_red[128];

    const int b = blockIdx.x;
    const int tid = threadIdx.x;
    const int* sb = seq + b * T;

    if (tid < VOCAB) {
        s_rankv[tid] = g_rank_of_vid[tid];
        s_vid[tid]   = g_vid_of_rank[tid];
        s_slot[tid]  = 0ull;
        s_wv[tid]    = 0.f;
    }
    const unsigned long long act = g_act_mask;
    __syncthreads();

    // ---- phase 1: order-preserving compaction of active tokens (warp 0) ----
    if (tid < 32) {
        int base = 0;
        #pragma unroll 4
        for (int it = 0; it < 64; ++it) {
            int t = it * 32 + tid;
            int v = 0;
            bool a = false;
            if (t < TLOOP) {
                v = sb[t];
                a = ((act >> v) & 1ull) != 0ull;
            }
            unsigned ball = __ballot_sync(0xffffffffu, a);
            if (a) {
                int pos = base + __popc(ball & ((1u << tid) - 1u));
                s_list[pos] = (uint8_t)s_rankv[v];
            }
            base += __popc(ball);
        }
        if (tid == 0) s_nact = base;
    }
    __syncthreads();

    // ---- phase 2: serial automaton (thread 0) ----
    if (tid == 0) {
        const int n = s_nact;
        unsigned long long present = 0ull;
        int fcnt = 0;
        int sw = 0;
        unsigned long long pack = 0ull;
        for (int i = 0; i < n; ++i) {
            if ((i & 7) == 0)
                pack = *reinterpret_cast<const unsigned long long*>(&s_list[i]);
            int r = (int)((pack >> ((i & 7) * 8)) & 0xff);
            if (fcnt < FAST) {
                // fast has free slots -> sequential fill
                int s = fcnt++;
                s_fast[s] = (uint8_t)r;
                s_slot[r] |= 1ull << s;
                present |= 1ull << r;
            } else {
                // demote min-dem present rank, first slot of it
                int pv = __ffsll((long long)present) - 1;
                unsigned long long m = s_slot[pv];
                int s = __ffsll((long long)m) - 1;
                unsigned long long m2 = m & (m - 1ull);
                s_slot[pv] = m2;
                unsigned long long pr = present;
                if (m2 == 0ull) pr &= ~(1ull << pv);
                unsigned long long mr = (r == pv) ? m2 : s_slot[r];
                s_slot[r] = mr | (1ull << s);
                present = pr | (1ull << r);
                // slow write: sequential fill then FIFO ring (exact argmax-age)
                s_slow[sw & (SLOW - 1)] = (uint8_t)pv;
                sw++;
                s_fast[s] = (uint8_t)r;
            }
        }
        s_fcnt = fcnt;
        s_swrites = sw;
    }
    __syncthreads();

    const int fcnt = s_fcnt;
    const int scnt = min(s_swrites, SLOW);
    const int cnt = fcnt + scnt;

    // ---- phase 3a: q = emb[last_tok] @ Wq + bq ----
    const int lv = sb[T - 1];
    const float* erow = emb + lv * HID;
    for (int j = tid; j < HID; j += 128) {
        float acc = bq[j];
        #pragma unroll 8
        for (int h = 0; h < HID; ++h) acc += erow[h] * Wq[h * HID + j];
        s_q[j] = acc;
    }
    __syncthreads();

    // ---- phase 3b: p[rank] = emb[vid(rank)] . q ----
    if (tid < VOCAB) {
        const float* er2 = emb + s_vid[tid] * HID;
        float acc = 0.f;
        #pragma unroll 8
        for (int h = 0; h < HID; ++h) acc += er2[h] * s_q[h];
        s_p[tid] = acc;
    }
    __syncthreads();

    // ---- phase 3c: masked softmax over occupied slots ----
    float mx = -3.402823466e38f;
    for (int nn = tid; nn < cnt; nn += 128) {
        int r = (nn < fcnt) ? (int)s_fast[nn] : (int)s_slow[nn - fcnt];
        mx = fmaxf(mx, s_p[r]);
    }
    s_red[tid] = mx;
    __syncthreads();
    #pragma unroll
    for (int off = 64; off > 0; off >>= 1) {
        if (tid < off) s_red[tid] = fmaxf(s_red[tid], s_red[tid + off]);
        __syncthreads();
    }
    mx = s_red[0];
    __syncthreads();

    float sum = 0.f;
    for (int nn = tid; nn < cnt; nn += 128) {
        int r = (nn < fcnt) ? (int)s_fast[nn] : (int)s_slow[nn - fcnt];
        sum += expf(s_p[r] - mx);
    }
    s_red[tid] = sum;
    __syncthreads();
    #pragma unroll
    for (int off = 64; off > 0; off >>= 1) {
        if (tid < off) s_red[tid] += s_red[tid + off];
        __syncthreads();
    }
    float inv = (cnt > 0) ? (1.f / s_red[0]) : 0.f;
    __syncthreads();

    for (int nn = tid; nn < cnt; nn += 128) {
        int r = (nn < fcnt) ? (int)s_fast[nn] : (int)s_slow[nn - fcnt];
        atomicAdd(&s_wv[s_vid[r]], expf(s_p[r] - mx) * inv);
    }
    __syncthreads();

    // ---- phase 3d: logits[j] = sum_v wv[v]*EWo[v][j] + bo[j] ----
    if (tid < VOCAB) {
        float acc = bo[tid];
        #pragma unroll 8
        for (int v = 0; v < VOCAB; ++v) acc += s_wv[v] * g_EWo[v * VOCAB + tid];
        out[b * VOCAB + tid] = acc;
    }
    // ---- slow_mask output (slots fill sequentially) ----
    for (int j = tid; j < SLOW; j += 128) {
        out[BATCH * VOCAB + b * SLOW + j] = (j < scnt) ? 1.f : 0.f;
    }
}

extern "C" void kernel_launch(void* const* d_in, const int* in_sizes, int n_in,
                              void* d_out, int out_size) {
    const int*   seq = (const int*)d_in[0];
    const float* emb = (const float*)d_in[1];
    const float* Wg  = (const float*)d_in[2];
    const float* bg  = (const float*)d_in[3];
    const float* Wd  = (const float*)d_in[4];
    const float* bd  = (const float*)d_in[5];
    const float* Wq  = (const float*)d_in[6];
    const float* bq  = (const float*)d_in[7];
    const float* Wo  = (const float*)d_in[8];
    const float* bo  = (const float*)d_in[9];
    float* out = (float*)d_out;

    prep_kernel<<<1, 256>>>(emb, Wg, bg, Wd, bd, Wo);
    main_kernel<<<BATCH, 128>>>(seq, emb, Wq, bq, bo, out);
}

// round 2
// speedup vs baseline: 1.7560x; 1.7560x over previous
#include <cuda_runtime.h>
#include <stdint.h>

#define BATCH 64
#define T 2048
#define HID 256
#define FAST 64
#define SLOW 256
#define VOCAB 64
#define TLOOP (T - 3)

typedef unsigned long long u64;

// Inter-kernel scratch (static device globals: allowed, no allocation)
__device__ u64   g_act_mask;
__device__ int   g_rank_of_vid[VOCAB];
__device__ int   g_vid_of_rank[VOCAB];
__device__ float g_EWo[VOCAB * VOCAB];   // [v][j] = emb[v] @ Wo
__device__ float g_EWq[VOCAB * HID];     // [u][h2] = emb[u] @ Wq
__device__ float g_EQEb[VOCAB * VOCAB];  // [u][v] = emb[v].(emb[u]@Wq) + emb[v].bq

// ---------------------------------------------------------------------------
// prepA: per-vocab act/dem/ranks (block 0), EWo and EWq (all blocks)
// ---------------------------------------------------------------------------
__global__ void prepA_kernel(const float* __restrict__ emb,
                             const float* __restrict__ Wg,
                             const float* __restrict__ bg,
                             const float* __restrict__ Wd,
                             const float* __restrict__ bd,
                             const float* __restrict__ Wq,
                             const float* __restrict__ Wo) {
    const int v = blockIdx.x;
    const int tid = threadIdx.x;
    const float* er = emb + v * HID;

    // EWq[v][j]
    {
        float acc = 0.f;
        #pragma unroll 8
        for (int h = 0; h < HID; ++h) acc += er[h] * Wq[h * HID + tid];
        g_EWq[v * HID + tid] = acc;
    }
    // EWo[v][j]
    if (tid < VOCAB) {
        float acc = 0.f;
        #pragma unroll 8
        for (int h = 0; h < HID; ++h) acc += er[h] * Wo[h * VOCAB + tid];
        g_EWo[v * VOCAB + tid] = acc;
    }

    if (blockIdx.x == 0) {
        __shared__ float s_dem[VOCAB];
        __shared__ unsigned int s_ball[2];
        if (tid < VOCAB) {
            const float* e2 = emb + tid * HID;
            float gd = 0.f, dd = 0.f;
            #pragma unroll 8
            for (int h = 0; h < HID; ++h) {
                float e = e2[h];
                gd += e * Wg[h];
                dd += e * Wd[h];
            }
            float x = gd + bg[0];
            float ws = 1.f / (1.f + expf(-x));
            s_dem[tid] = dd + bd[0];
            unsigned bal = __ballot_sync(0xffffffffu, ws >= 0.4f);
            if ((tid & 31) == 0) s_ball[tid >> 5] = bal;
        }
        __syncthreads();
        if (tid == 0)
            g_act_mask = (u64)s_ball[0] | ((u64)s_ball[1] << 32);
        if (tid < VOCAB) {
            float dv = s_dem[tid];
            int rank = 0;
            for (int u = 0; u < VOCAB; ++u) {
                float du = s_dem[u];
                if (du < dv || (du == dv && u < tid)) rank++;
            }
            g_rank_of_vid[tid] = rank;
            g_vid_of_rank[rank] = tid;
        }
    }
}

// ---------------------------------------------------------------------------
// prepB: EQEb[u][v] = emb[v] . EWq[u] + emb[v].bq   (block = v)
// ---------------------------------------------------------------------------
__global__ void prepB_kernel(const float* __restrict__ emb,
                             const float* __restrict__ bq) {
    __shared__ float s_e[HID];
    __shared__ float s_red[HID];
    const int v = blockIdx.x;
    const int tid = threadIdx.x;

    s_e[tid] = emb[v * HID + tid];
    s_red[tid] = emb[v * HID + tid] * bq[tid];
    __syncthreads();
    #pragma unroll
    for (int off = 128; off > 0; off >>= 1) {
        if (tid < off) s_red[tid] += s_red[tid + off];
        __syncthreads();
    }
    const float ebq = s_red[0];

    if (tid < VOCAB) {
        const float* wr = g_EWq + tid * HID;
        float acc = 0.f;
        #pragma unroll 8
        for (int h = 0; h < HID; ++h) acc += s_e[h] * wr[h];
        g_EQEb[tid * VOCAB + v] = acc + ebq;
    }
}

// ---------------------------------------------------------------------------
// main: one block per batch.
//  phase 1: 4 warps compact active token ranks (order-preserving, 2-pass)
//  phase 2: thread 0 runs register-only bitmask automaton (P/D masks)
//  phase 3: table-lookup read head: softmax over rank counts, 64x64 matvec
// ---------------------------------------------------------------------------
__global__ void __launch_bounds__(128) main_kernel(
    const int* __restrict__ seq,
    const float* __restrict__ bo,
    float* __restrict__ out) {

    __shared__ __align__(8) uint8_t s_list[2048 + 8];
    __shared__ uint8_t s_slow[SLOW];     // demotion ring (rank per eviction)
    __shared__ int s_cnt[VOCAB];         // fast counts for ranks with D-bit set
    __shared__ int s_hist[VOCAB];        // slow histogram per rank
    __shared__ int s_rankv[VOCAB];
    __shared__ int s_vid[VOCAB];
    __shared__ int s_wcnt[4];
    __shared__ int s_nact, s_swr;
    __shared__ u64 s_P, s_D;
    __shared__ float s_w[VOCAB];
    __shared__ float s_r4[4];

    const int b = blockIdx.x;
    const int tid = threadIdx.x;
    const int wid = tid >> 5, lane = tid & 31;
    const int* sb = seq + b * T;
    const u64 act = g_act_mask;

    if (tid < VOCAB) {
        s_rankv[tid] = g_rank_of_vid[tid];
        s_vid[tid]   = g_vid_of_rank[tid];
        s_hist[tid]  = 0;
    }
    __syncthreads();

    // ---- phase 1: order-preserving compaction, 4 warps, 2 passes ----
    const int base_t = wid * 512;
    {
        int cl = 0;
        #pragma unroll 4
        for (int it = 0; it < 16; ++it) {
            int t = base_t + it * 32 + lane;
            bool a = false;
            if (t < TLOOP) {
                int v = sb[t];
                a = ((act >> v) & 1ull) != 0ull;
            }
            cl += __popc(__ballot_sync(0xffffffffu, a));
        }
        if (lane == 0) s_wcnt[wid] = cl;
    }
    __syncthreads();
    {
        int off = 0;
        for (int w = 0; w < wid; ++w) off += s_wcnt[w];
        int pos = off;
        #pragma unroll 4
        for (int it = 0; it < 16; ++it) {
            int t = base_t + it * 32 + lane;
            bool a = false; int v = 0;
            if (t < TLOOP) {
                v = sb[t];
                a = ((act >> v) & 1ull) != 0ull;
            }
            unsigned ball = __ballot_sync(0xffffffffu, a);
            if (a)
                s_list[pos + __popc(ball & ((1u << lane) - 1u))] =
                    (uint8_t)s_rankv[v];
            pos += __popc(ball);
        }
        if (tid == 0)
            s_nact = s_wcnt[0] + s_wcnt[1] + s_wcnt[2] + s_wcnt[3];
    }
    __syncthreads();

    // ---- phase 2: serial automaton on thread 0, register-resident masks ----
    if (tid == 0) {
        const int n = s_nact;
        u64 P = 0ull, D = 0ull;
        const int nf = (n < FAST) ? n : FAST;
        // fill phase: pure multiset inserts
        for (int i = 0; i < nf; ++i) {
            int r = s_list[i];
            u64 bit = 1ull << r;
            if (P & bit) {
                if (D & bit) s_cnt[r] = s_cnt[r] + 1;
                else { D |= bit; s_cnt[r] = 2; }
            } else P |= bit;
        }
        int sw = 0;
        if (n > FAST) {
            const u64* lp = reinterpret_cast<const u64*>(s_list);
            const int rem = n - FAST;
            const int fullp = rem >> 3;
            const int tail = rem & 7;
            int pkI = FAST >> 3;
            for (int bb = 0; bb <= fullp; ++bb) {
                u64 pack = lp[pkI + bb];
                const int kmax = (bb < fullp) ? 8 : tail;
                #pragma unroll 8
                for (int k = 0; k < 8; ++k) {
                    if (k >= kmax) break;
                    const int r = (int)((pack >> (k * 8)) & 63u);
                    const u64 bit = 1ull << r;
                    // evict min present rank (index-free on the chain)
                    const u64 iso = P & (0ull - P);
                    const int pv = __popcll(iso - 1ull);   // off-chain
                    s_slow[sw & (SLOW - 1)] = (uint8_t)pv; // off-chain
                    ++sw;
                    u64 Pn, Dn;
                    if (D & iso) {
                        int c = s_cnt[pv] - 1;
                        s_cnt[pv] = c;
                        Dn = (c == 1) ? (D ^ iso) : D;
                        Pn = P;
                    } else {
                        Pn = P ^ iso;
                        Dn = D;
                    }
                    // insert r
                    if (Pn & bit) {
                        if (Dn & bit) s_cnt[r] = s_cnt[r] + 1;
                        else { Dn |= bit; s_cnt[r] = 2; }
                    } else Pn |= bit;
                    P = Pn; D = Dn;
                }
            }
        }
        s_swr = sw;
        s_P = P;
        s_D = D;
    }
    __syncthreads();

    const int sw = s_swr;
    const int scnt = (sw < SLOW) ? sw : SLOW;

    // ---- phase 3: read head ----
    // histogram of demotion ring
    for (int k = tid; k < scnt; k += 128)
        atomicAdd(&s_hist[(int)s_slow[k]], 1);
    __syncthreads();

    const int lv = sb[T - 1];

    int ct = 0;
    float p = 0.f;
    if (tid < VOCAB) {
        const u64 P = s_P, D = s_D;
        int fc = ((P >> tid) & 1ull)
                     ? (((D >> tid) & 1ull) ? s_cnt[tid] : 1)
                     : 0;
        ct = fc + s_hist[tid];
        p = g_EQEb[lv * VOCAB + s_vid[tid]];
    }

    // block max over (ct>0 ? p : -inf)
    float v = (tid < VOCAB && ct > 0) ? p : -3.402823466e38f;
    #pragma unroll
    for (int off = 16; off > 0; off >>= 1)
        v = fmaxf(v, __shfl_xor_sync(0xffffffffu, v, off));
    if (lane == 0) s_r4[wid] = v;
    __syncthreads();
    const float mx = fmaxf(fmaxf(s_r4[0], s_r4[1]), fmaxf(s_r4[2], s_r4[3]));
    __syncthreads();

    float e = (tid < VOCAB && ct > 0) ? (float)ct * expf(p - mx) : 0.f;
    float sm = e;
    #pragma unroll
    for (int off = 16; off > 0; off >>= 1)
        sm += __shfl_xor_sync(0xffffffffu, sm, off);
    if (lane == 0) s_r4[wid] = sm;
    __syncthreads();
    const float tot = s_r4[0] + s_r4[1] + s_r4[2] + s_r4[3];
    const float inv = (tot > 0.f) ? (1.f / tot) : 0.f;
    if (tid < VOCAB) s_w[tid] = e * inv;
    __syncthreads();

    // logits[j] = bo[j] + sum_r w[r] * EWo[vid[r]][j]
    if (tid < VOCAB) {
        float acc = bo[tid];
        #pragma unroll 8
        for (int r = 0; r < VOCAB; ++r)
            acc += s_w[r] * g_EWo[s_vid[r] * VOCAB + tid];
        out[b * VOCAB + tid] = acc;
    }
    // slow_mask: slow slots fill sequentially
    for (int j = tid; j < SLOW; j += 128)
        out[BATCH * VOCAB + b * SLOW + j] = (j < scnt) ? 1.f : 0.f;
}

extern "C" void kernel_launch(void* const* d_in, const int* in_sizes, int n_in,
                              void* d_out, int out_size) {
    const int*   seq = (const int*)d_in[0];
    const float* emb = (const float*)d_in[1];
    const float* Wg  = (const float*)d_in[2];
    const float* bg  = (const float*)d_in[3];
    const float* Wd  = (const float*)d_in[4];
    const float* bd  = (const float*)d_in[5];
    const float* Wq  = (const float*)d_in[6];
    const float* bq  = (const float*)d_in[7];
    const float* Wo  = (const float*)d_in[8];
    const float* bo  = (const float*)d_in[9];
    float* out = (float*)d_out;

    prepA_kernel<<<VOCAB, HID>>>(emb, Wg, bg, Wd, bd, Wq, Wo);
    prepB_kernel<<<VOCAB, HID>>>(emb, bq);
    main_kernel<<<BATCH, 128>>>(seq, bo, out);
}

// round 3
// speedup vs baseline: 2.7581x; 1.5707x over previous
#include <cuda_runtime.h>
#include <stdint.h>

#define BATCH 64
#define T 2048
#define HID 256
#define FAST 64
#define SLOW 256
#define VOCAB 64
#define TLOOP (T - 3)

typedef unsigned long long u64;

// ---------------------------------------------------------------------------
// Single fused kernel: one block per batch, 128 threads.
//   step 0: all warps cooperatively compute act/dem per vocab + ranks (L2-hot)
//   step 1: 4-warp order-preserving compaction of active token ranks
//   step 2: warp 0 thread 0 runs the bitmask automaton;
//           warps 1-3 concurrently compute q = emb[lv]@Wq+bq and p[rank]
//   step 3: softmax over rank counts, ctx = sum w*emb, logits = ctx@Wo + bo
// ---------------------------------------------------------------------------
__global__ void __launch_bounds__(128) fused_kernel(
    const int* __restrict__ seq,
    const float* __restrict__ emb,
    const float* __restrict__ Wg, const float* __restrict__ bg,
    const float* __restrict__ Wd, const float* __restrict__ bd,
    const float* __restrict__ Wq, const float* __restrict__ bq,
    const float* __restrict__ Wo, const float* __restrict__ bo,
    float* __restrict__ out)
{
    __shared__ __align__(8) uint8_t s_list[2048 + 8];
    __shared__ uint8_t s_slow[SLOW];
    __shared__ int s_cnt[VOCAB];       // fast counts (valid where D-bit set)
    __shared__ int s_hist[VOCAB];      // slow-ring histogram
    __shared__ float s_dem[VOCAB];
    __shared__ int s_rankv[VOCAB];     // vid -> rank
    __shared__ int s_vid[VOCAB];       // rank -> vid
    __shared__ unsigned s_am[2];
    __shared__ int s_wcnt[4];
    __shared__ int s_nact, s_swr;
    __shared__ u64 s_P, s_D;
    __shared__ float s_q[HID];
    __shared__ float s_elv[HID];
    __shared__ float s_ctx[HID];
    __shared__ float s_p[VOCAB];
    __shared__ float s_w[VOCAB];
    __shared__ float s_r4[4];

    const int b = blockIdx.x;
    const int tid = threadIdx.x;
    const int wid = tid >> 5, lane = tid & 31;
    const int* sb = seq + b * T;

    if (tid < 2) s_am[tid] = 0u;
    if (tid < VOCAB) s_hist[tid] = 0;
    __syncthreads();

    const int lv = sb[T - 1];

    // ---- step 0: act/dem per vocab (warp-cooperative coalesced dots) ----
    {
        const float bg0 = bg[0];
        const float bd0 = bd[0];
        #pragma unroll
        for (int rr = 0; rr < 16; ++rr) {
            const int row = wid * 16 + rr;
            const float* er = emb + row * HID;
            float ag = 0.f, ad = 0.f;
            #pragma unroll
            for (int k = 0; k < 8; ++k) {
                float e = er[lane + 32 * k];
                ag += e * Wg[lane + 32 * k];
                ad += e * Wd[lane + 32 * k];
            }
            #pragma unroll
            for (int off = 16; off > 0; off >>= 1) {
                ag += __shfl_xor_sync(0xffffffffu, ag, off);
                ad += __shfl_xor_sync(0xffffffffu, ad, off);
            }
            if (lane == 0) {
                s_dem[row] = ad + bd0;
                float x = ag + bg0;
                float ws = 1.f / (1.f + expf(-x));
                unsigned bit = (ws >= 0.4f) ? (1u << (row & 31)) : 0u;
                atomicOr(&s_am[row >> 5], bit);
            }
        }
    }
    // load emb[lv] into smem (all threads)
    for (int h = tid; h < HID; h += 128) s_elv[h] = emb[lv * HID + h];
    __syncthreads();

    // ranks by ascending dem (tie: lower vid)
    if (tid < VOCAB) {
        float dv = s_dem[tid];
        int rank = 0;
        #pragma unroll 8
        for (int u = 0; u < VOCAB; ++u) {
            float du = s_dem[u];
            if (du < dv || (du == dv && u < tid)) rank++;
        }
        s_rankv[tid] = rank;
        s_vid[rank] = tid;
    }
    __syncthreads();

    const u64 act = (u64)s_am[0] | ((u64)s_am[1] << 32);

    // ---- step 1: order-preserving compaction (4 warps, 2 passes) ----
    const int base_t = wid * 512;
    {
        int cl = 0;
        #pragma unroll 4
        for (int it = 0; it < 16; ++it) {
            int t = base_t + it * 32 + lane;
            bool a = false;
            if (t < TLOOP) {
                int v = sb[t];
                a = ((act >> v) & 1ull) != 0ull;
            }
            cl += __popc(__ballot_sync(0xffffffffu, a));
        }
        if (lane == 0) s_wcnt[wid] = cl;
    }
    __syncthreads();
    {
        int off = 0;
        for (int w = 0; w < wid; ++w) off += s_wcnt[w];
        int pos = off;
        #pragma unroll 4
        for (int it = 0; it < 16; ++it) {
            int t = base_t + it * 32 + lane;
            bool a = false; int v = 0;
            if (t < TLOOP) {
                v = sb[t];
                a = ((act >> v) & 1ull) != 0ull;
            }
            unsigned ball = __ballot_sync(0xffffffffu, a);
            if (a)
                s_list[pos + __popc(ball & ((1u << lane) - 1u))] =
                    (uint8_t)s_rankv[v];
            pos += __popc(ball);
        }
        if (tid == 0)
            s_nact = s_wcnt[0] + s_wcnt[1] + s_wcnt[2] + s_wcnt[3];
    }
    __syncthreads();

    // ---- step 2: automaton on warp 0 || q,p on warps 1-3 ----
    if (wid == 0) {
        if (lane == 0) {
            const int n = s_nact;
            u64 P = 0ull, D = 0ull;
            const int nf = (n < FAST) ? n : FAST;
            for (int i = 0; i < nf; ++i) {
                int r = s_list[i];
                u64 bit = 1ull << r;
                u64 inp = P & bit;
                if (inp) s_cnt[r] = (D & bit) ? (s_cnt[r] + 1) : 2;
                D |= inp;
                P |= bit;
            }
            int sw = 0;
            if (n > FAST) {
                const u64* lp = reinterpret_cast<const u64*>(s_list);
                u64 pack = 0ull;
                for (int i = FAST; i < n; ++i) {
                    if ((i & 7) == 0) pack = lp[i >> 3];
                    const int r = (int)(pack >> ((i & 7) * 8)) & 63;
                    const u64 bit = 1ull << r;
                    // evict min present rank
                    const u64 iso = P & (0ull - P);
                    const int pv = __popcll(iso - 1ull);      // off-chain
                    s_slow[sw & (SLOW - 1)] = (uint8_t)pv;    // off-chain
                    ++sw;
                    const u64 md = D & iso;
                    P ^= (iso ^ md);                          // branchless P
                    if (md) {                                 // rare path
                        int c = s_cnt[pv] - 1;
                        s_cnt[pv] = c;
                        if (c == 1) D ^= iso;
                    }
                    // insert r
                    const u64 inp = P & bit;
                    if (inp) s_cnt[r] = (D & bit) ? (s_cnt[r] + 1) : 2;
                    D |= inp;
                    P |= bit;
                }
            }
            s_swr = sw;
            s_P = P;
            s_D = D;
        }
    } else {
        // q[j] = bq[j] + sum_h elv[h]*Wq[h][j]   (96 threads, coalesced j)
        const int i = tid - 32;                 // 0..95, warp-uniform i<64
        float a0 = bq[i];
        float a1 = bq[i + 96];
        float a2 = (i < 64) ? bq[i + 192] : 0.f;
        #pragma unroll 4
        for (int h = 0; h < HID; ++h) {
            const float e = s_elv[h];
            const float* row = Wq + h * HID;
            a0 += e * row[i];
            a1 += e * row[i + 96];
            if (i < 64) a2 += e * row[i + 192];
        }
        s_q[i] = a0;
        s_q[i + 96] = a1;
        if (i < 64) s_q[i + 192] = a2;
        asm volatile("bar.sync 1, 96;" ::: "memory");
        // p[rank] = emb[vid(rank)] . q
        if (i < 64) {
            const float* er = emb + s_vid[i] * HID;
            float acc = 0.f;
            #pragma unroll 8
            for (int h = 0; h < HID; ++h) acc += er[h] * s_q[h];
            s_p[i] = acc;
        }
    }
    __syncthreads();

    const int sw = s_swr;
    const int scnt = (sw < SLOW) ? sw : SLOW;

    // ---- step 3: read head ----
    for (int k = tid; k < scnt; k += 128)
        atomicAdd(&s_hist[(int)s_slow[k]], 1);
    __syncthreads();

    int ct = 0;
    float p = 0.f;
    if (tid < VOCAB) {
        const u64 P = s_P, D = s_D;
        int fc = ((P >> tid) & 1ull)
                     ? (((D >> tid) & 1ull) ? s_cnt[tid] : 1)
                     : 0;
        ct = fc + s_hist[tid];
        p = s_p[tid];
    }

    float v = (tid < VOCAB && ct > 0) ? p : -3.402823466e38f;
    #pragma unroll
    for (int off = 16; off > 0; off >>= 1)
        v = fmaxf(v, __shfl_xor_sync(0xffffffffu, v, off));
    if (lane == 0) s_r4[wid] = v;
    __syncthreads();
    const float mx = fmaxf(fmaxf(s_r4[0], s_r4[1]), fmaxf(s_r4[2], s_r4[3]));
    __syncthreads();

    float e = (tid < VOCAB && ct > 0) ? (float)ct * expf(p - mx) : 0.f;
    float sm = e;
    #pragma unroll
    for (int off = 16; off > 0; off >>= 1)
        sm += __shfl_xor_sync(0xffffffffu, sm, off);
    if (lane == 0) s_r4[wid] = sm;
    __syncthreads();
    const float tot = s_r4[0] + s_r4[1] + s_r4[2] + s_r4[3];
    const float inv = (tot > 0.f) ? (1.f / tot) : 0.f;
    if (tid < VOCAB) s_w[tid] = e * inv;
    __syncthreads();

    // ctx[h] = sum_r w[r] * emb[vid[r]][h]   (coalesced h per r)
    {
        float c0 = 0.f, c1 = 0.f;
        #pragma unroll 8
        for (int r = 0; r < VOCAB; ++r) {
            const float w = s_w[r];
            const float* er = emb + s_vid[r] * HID;
            c0 += w * er[tid];
            c1 += w * er[tid + 128];
        }
        s_ctx[tid] = c0;
        s_ctx[tid + 128] = c1;
    }
    __syncthreads();

    // logits[j] = bo[j] + ctx . Wo[:,j]   (128 threads: j = tid&63, 2 halves)
    {
        const int j = tid & 63;
        const int half = tid >> 6;
        float acc = 0.f;
        #pragma unroll 8
        for (int k = 0; k < 128; ++k) {
            const int h = half * 128 + k;
            acc += s_ctx[h] * Wo[h * VOCAB + j];
        }
        #pragma unroll
        for (int off = 16; off > 0; off >>= 1) {
            // halves of same j live 64 apart -> combine via smem
        }
        s_r4[0] = s_r4[0]; // no-op to keep structure
        // combine the two halves through shared memory
        __shared__ float s_half[128];
        s_half[tid] = acc;
        __syncthreads();
        if (tid < VOCAB)
            out[b * VOCAB + tid] = bo[tid] + s_half[tid] + s_half[tid + 64];
    }

    // slow_mask: slow slots fill sequentially
    for (int j = tid; j < SLOW; j += 128)
        out[BATCH * VOCAB + b * SLOW + j] = (j < scnt) ? 1.f : 0.f;
}

extern "C" void kernel_launch(void* const* d_in, const int* in_sizes, int n_in,
                              void* d_out, int out_size) {
    const int*   seq = (const int*)d_in[0];
    const float* emb = (const float*)d_in[1];
    const float* Wg  = (const float*)d_in[2];
    const float* bg  = (const float*)d_in[3];
    const float* Wd  = (const float*)d_in[4];
    const float* bd  = (const float*)d_in[5];
    const float* Wq  = (const float*)d_in[6];
    const float* bq  = (const float*)d_in[7];
    const float* Wo  = (const float*)d_in[8];
    const float* bo  = (const float*)d_in[9];
    float* out = (float*)d_out;

    fused_kernel<<<BATCH, 128>>>(seq, emb, Wg, bg, Wd, bd, Wq, bq, Wo, bo, out);
}

// round 4
// speedup vs baseline: 3.3175x; 1.2028x over previous
#include <cuda_runtime.h>
#include <stdint.h>

#define BATCH 64
#define T 2048
#define HID 256
#define FAST 64
#define SLOW 256
#define VOCAB 64
#define TLOOP (T - 3)

typedef unsigned long long u64;

__global__ void __launch_bounds__(128) fused_kernel(
    const int* __restrict__ seq,
    const float* __restrict__ emb,
    const float* __restrict__ Wg, const float* __restrict__ bg,
    const float* __restrict__ Wd, const float* __restrict__ bd,
    const float* __restrict__ Wq, const float* __restrict__ bq,
    const float* __restrict__ Wo, const float* __restrict__ bo,
    float* __restrict__ out)
{
    __shared__ __align__(8) uint8_t s_list[2048 + 8];
    __shared__ uint8_t s_slow[SLOW];
    __shared__ int s_cnt[VOCAB];       // fast counts (valid where D-bit set)
    __shared__ int s_hist[VOCAB];      // slow-ring histogram
    __shared__ float s_dem[VOCAB];
    __shared__ int s_rankv[VOCAB];     // vid -> rank
    __shared__ int s_vid[VOCAB];       // rank -> vid
    __shared__ unsigned s_am[2];
    __shared__ int s_wcnt[4];
    __shared__ int s_nact, s_swr;
    __shared__ u64 s_P, s_D;
    __shared__ float s_q[HID];
    __shared__ float s_elv[HID];
    __shared__ float s_ctx[HID];
    __shared__ float s_p[VOCAB];
    __shared__ float s_w[VOCAB];
    __shared__ float s_r4[4];
    __shared__ float s_half[128];

    const int b = blockIdx.x;
    const int tid = threadIdx.x;
    const int wid = tid >> 5, lane = tid & 31;
    const int* sb = seq + b * T;

    if (tid < 2) s_am[tid] = 0u;
    if (tid < VOCAB) s_hist[tid] = 0;
    __syncthreads();

    const int lv = sb[T - 1];

    // ---- step 0: act/dem per vocab (warp-cooperative coalesced dots) ----
    {
        const float bg0 = bg[0];
        const float bd0 = bd[0];
        #pragma unroll
        for (int rr = 0; rr < 16; ++rr) {
            const int row = wid * 16 + rr;
            const float* er = emb + row * HID;
            float ag = 0.f, ad = 0.f;
            #pragma unroll
            for (int k = 0; k < 8; ++k) {
                float e = er[lane + 32 * k];
                ag += e * Wg[lane + 32 * k];
                ad += e * Wd[lane + 32 * k];
            }
            #pragma unroll
            for (int off = 16; off > 0; off >>= 1) {
                ag += __shfl_xor_sync(0xffffffffu, ag, off);
                ad += __shfl_xor_sync(0xffffffffu, ad, off);
            }
            if (lane == 0) {
                s_dem[row] = ad + bd0;
                float x = ag + bg0;
                float ws = 1.f / (1.f + expf(-x));
                unsigned bit = (ws >= 0.4f) ? (1u << (row & 31)) : 0u;
                atomicOr(&s_am[row >> 5], bit);
            }
        }
    }
    for (int h = tid; h < HID; h += 128) s_elv[h] = emb[lv * HID + h];
    __syncthreads();

    // ranks by ascending dem (tie: lower vid)
    if (tid < VOCAB) {
        float dv = s_dem[tid];
        int rank = 0;
        #pragma unroll 8
        for (int u = 0; u < VOCAB; ++u) {
            float du = s_dem[u];
            if (du < dv || (du == dv && u < tid)) rank++;
        }
        s_rankv[tid] = rank;
        s_vid[rank] = tid;
    }
    __syncthreads();

    const u64 act = (u64)s_am[0] | ((u64)s_am[1] << 32);

    // ---- step 1: order-preserving compaction (4 warps, 2 passes) ----
    const int base_t = wid * 512;
    {
        int cl = 0;
        #pragma unroll 4
        for (int it = 0; it < 16; ++it) {
            int t = base_t + it * 32 + lane;
            bool a = false;
            if (t < TLOOP) {
                int v = sb[t];
                a = ((act >> v) & 1ull) != 0ull;
            }
            cl += __popc(__ballot_sync(0xffffffffu, a));
        }
        if (lane == 0) s_wcnt[wid] = cl;
    }
    __syncthreads();
    {
        int off = 0;
        for (int w = 0; w < wid; ++w) off += s_wcnt[w];
        int pos = off;
        #pragma unroll 4
        for (int it = 0; it < 16; ++it) {
            int t = base_t + it * 32 + lane;
            bool a = false; int v = 0;
            if (t < TLOOP) {
                v = sb[t];
                a = ((act >> v) & 1ull) != 0ull;
            }
            unsigned ball = __ballot_sync(0xffffffffu, a);
            if (a)
                s_list[pos + __popc(ball & ((1u << lane) - 1u))] =
                    (uint8_t)s_rankv[v];
            pos += __popc(ball);
        }
        if (tid == 0)
            s_nact = s_wcnt[0] + s_wcnt[1] + s_wcnt[2] + s_wcnt[3];
    }
    __syncthreads();

    // ---- step 2: automaton on warp 0 lane 0 || q,p on warps 1-3 ----
    if (wid == 0) {
        if (lane == 0) {
            const int n = s_nact;
            u64 P = 0ull, D = 0ull;
            const int nf = (n < FAST) ? n : FAST;

            // fill phase: branchless multiset insert
            for (int i = 0; i < nf; ++i) {
                const int r = s_list[i];
                const u64 bit = 1ull << r;
                const u64 inp = P & bit;
                const u64 db  = D & bit;
                const int cr  = s_cnt[r];
                s_cnt[r] = db ? (cr + 1) : 2;   // garbage-safe when !inp
                D |= inp;
                P |= bit;
            }

            int sw = 0;
            if (n > FAST) {
                const u64* lp = reinterpret_cast<const u64*>(s_list);

                // fully branchless steady-state step
                #define AUTO_STEP(RB) do {                                   \
                    const int r   = (int)(RB) & 63;                          \
                    const u64 bit = 1ull << r;                               \
                    const u64 iso = P & (0ull - P);                          \
                    const u64 md  = D & iso;                                 \
                    const int pv  = __popcll(iso - 1ull);                    \
                    s_slow[sw & (SLOW - 1)] = (uint8_t)pv;                   \
                    ++sw;                                                    \
                    const int c  = s_cnt[pv];                                \
                    const int cm = c - 1;                                    \
                    s_cnt[pv] = cm;            /* garbage-safe when !md */   \
                    D ^= (cm == 1) ? md : 0ull;                              \
                    P ^= (iso ^ md);                                         \
                    const u64 inp = P & bit;                                 \
                    const u64 db  = D & bit;                                 \
                    const int cr  = s_cnt[r];                                \
                    s_cnt[r] = db ? (cr + 1) : 2; /* garbage-safe if !inp */ \
                    D |= inp;                                                \
                    P |= bit;                                                \
                } while (0)

                const int rem   = n - FAST;
                const int nmain = FAST + (rem & ~7);
                int i = FAST;
                for (; i < nmain; i += 8) {
                    const u64 pack = lp[i >> 3];   // FAST=64 is 8-aligned
                    AUTO_STEP(pack);
                    AUTO_STEP(pack >> 8);
                    AUTO_STEP(pack >> 16);
                    AUTO_STEP(pack >> 24);
                    AUTO_STEP(pack >> 32);
                    AUTO_STEP(pack >> 40);
                    AUTO_STEP(pack >> 48);
                    AUTO_STEP(pack >> 56);
                }
                for (; i < n; ++i) {
                    const uint8_t rb = s_list[i];
                    AUTO_STEP(rb);
                }
                #undef AUTO_STEP
            }
            s_swr = sw;
            s_P = P;
            s_D = D;
        }
    } else {
        // q[j] = bq[j] + sum_h elv[h]*Wq[h][j]   (96 threads)
        const int i = tid - 32;                 // 0..95
        float a0 = bq[i];
        float a1 = bq[i + 96];
        float a2 = (i < 64) ? bq[i + 192] : 0.f;
        #pragma unroll 4
        for (int h = 0; h < HID; ++h) {
            const float e = s_elv[h];
            const float* row = Wq + h * HID;
            a0 += e * row[i];
            a1 += e * row[i + 96];
            if (i < 64) a2 += e * row[i + 192];
        }
        s_q[i] = a0;
        s_q[i + 96] = a1;
        if (i < 64) s_q[i + 192] = a2;
        asm volatile("bar.sync 1, 96;" ::: "memory");
        // p[rank] = emb[vid(rank)] . q
        if (i < 64) {
            const float* er = emb + s_vid[i] * HID;
            float acc = 0.f;
            #pragma unroll 8
            for (int h = 0; h < HID; ++h) acc += er[h] * s_q[h];
            s_p[i] = acc;
        }
    }
    __syncthreads();

    const int sw = s_swr;
    const int scnt = (sw < SLOW) ? sw : SLOW;

    // ---- step 3: read head ----
    for (int k = tid; k < scnt; k += 128)
        atomicAdd(&s_hist[(int)s_slow[k]], 1);
    __syncthreads();

    int ct = 0;
    float p = 0.f;
    if (tid < VOCAB) {
        const u64 P = s_P, D = s_D;
        int fc = ((P >> tid) & 1ull)
                     ? (((D >> tid) & 1ull) ? s_cnt[tid] : 1)
                     : 0;
        ct = fc + s_hist[tid];
        p = s_p[tid];
    }

    float v = (tid < VOCAB && ct > 0) ? p : -3.402823466e38f;
    #pragma unroll
    for (int off = 16; off > 0; off >>= 1)
        v = fmaxf(v, __shfl_xor_sync(0xffffffffu, v, off));
    if (lane == 0) s_r4[wid] = v;
    __syncthreads();
    const float mx = fmaxf(fmaxf(s_r4[0], s_r4[1]), fmaxf(s_r4[2], s_r4[3]));
    __syncthreads();

    float e = (tid < VOCAB && ct > 0) ? (float)ct * expf(p - mx) : 0.f;
    float sm = e;
    #pragma unroll
    for (int off = 16; off > 0; off >>= 1)
        sm += __shfl_xor_sync(0xffffffffu, sm, off);
    if (lane == 0) s_r4[wid] = sm;
    __syncthreads();
    const float tot = s_r4[0] + s_r4[1] + s_r4[2] + s_r4[3];
    const float inv = (tot > 0.f) ? (1.f / tot) : 0.f;
    if (tid < VOCAB) s_w[tid] = e * inv;
    __syncthreads();

    // ctx[h] = sum_r w[r] * emb[vid[r]][h]
    {
        float c0 = 0.f, c1 = 0.f;
        #pragma unroll 8
        for (int r = 0; r < VOCAB; ++r) {
            const float w = s_w[r];
            const float* er = emb + s_vid[r] * HID;
            c0 += w * er[tid];
            c1 += w * er[tid + 128];
        }
        s_ctx[tid] = c0;
        s_ctx[tid + 128] = c1;
    }
    __syncthreads();

    // logits[j] = bo[j] + ctx . Wo[:,j]
    {
        const int j = tid & 63;
        const int half = tid >> 6;
        float acc = 0.f;
        #pragma unroll 8
        for (int k = 0; k < 128; ++k) {
            const int h = half * 128 + k;
            acc += s_ctx[h] * Wo[h * VOCAB + j];
        }
        s_half[tid] = acc;
        __syncthreads();
        if (tid < VOCAB)
            out[b * VOCAB + tid] = bo[tid] + s_half[tid] + s_half[tid + 64];
    }

    // slow_mask: slow slots fill sequentially
    for (int j = tid; j < SLOW; j += 128)
        out[BATCH * VOCAB + b * SLOW + j] = (j < scnt) ? 1.f : 0.f;
}

extern "C" void kernel_launch(void* const* d_in, const int* in_sizes, int n_in,
                              void* d_out, int out_size) {
    const int*   seq = (const int*)d_in[0];
    const float* emb = (const float*)d_in[1];
    const float* Wg  = (const float*)d_in[2];
    const float* bg  = (const float*)d_in[3];
    const float* Wd  = (const float*)d_in[4];
    const float* bd  = (const float*)d_in[5];
    const float* Wq  = (const float*)d_in[6];
    const float* bq  = (const float*)d_in[7];
    const float* Wo  = (const float*)d_in[8];
    const float* bo  = (const float*)d_in[9];
    float* out = (float*)d_out;

    fused_kernel<<<BATCH, 128>>>(seq, emb, Wg, bg, Wd, bd, Wq, bq, Wo, bo, out);
}

// round 5
// speedup vs baseline: 14.2236x; 4.2875x over previous
#include <cuda_runtime.h>
#include <stdint.h>

#define BATCH 64
#define T 2048
#define HID 256
#define FAST 64
#define SLOW 256
#define VOCAB 64
#define TLOOP (T - 3)

typedef unsigned long long u64;

__global__ void __launch_bounds__(256) fused_kernel(
    const int* __restrict__ seq,
    const float* __restrict__ emb,
    const float* __restrict__ Wg, const float* __restrict__ bg,
    const float* __restrict__ Wd, const float* __restrict__ bd,
    const float* __restrict__ Wq, const float* __restrict__ bq,
    const float* __restrict__ Wo, const float* __restrict__ bo,
    float* __restrict__ out)
{
    __shared__ float s_dem[VOCAB];
    __shared__ int s_rankv[VOCAB];       // vid -> rank (ascending dem)
    __shared__ int s_vid[VOCAB];         // rank -> vid
    __shared__ unsigned s_am[2];
    __shared__ uint8_t s_tok[2048];      // per-position: rank or 0xFF
    __shared__ int s_ccnt[64];           // active count per 32-chunk
    __shared__ int s_cpre[64];           // exclusive prefix
    __shared__ int s_ha[VOCAB];          // hist of all active (by rank)
    __shared__ int s_ht[VOCAB];          // hist of last 256 before y_m
    __shared__ int s_h1[VOCAB];          // hist(y_1..y_{m-1})
    __shared__ int s_h2[VOCAB];          // hist(y_1..y_{m-257})
    __shared__ int s_mrank, s_m;
    __shared__ float s_elv[HID];
    __shared__ float s_q[HID];
    __shared__ float s_ctx[HID];
    __shared__ float s_p[VOCAB];
    __shared__ float s_w[VOCAB];
    __shared__ float s_r8[8];
    __shared__ float s_half[256];

    const int b = blockIdx.x;
    const int tid = threadIdx.x;
    const int wid = tid >> 5, lane = tid & 31;
    const int* sb = seq + b * T;

    if (tid < 2) s_am[tid] = 0u;
    if (tid < VOCAB) { s_ha[tid] = 0; s_ht[tid] = 0; }
    if (tid == 0) s_mrank = -1;
    __syncthreads();

    const int lv = sb[T - 1];

    // ---- gate/demotion scores per vocab (8 warps x 8 rows, coalesced) ----
    {
        const float bg0 = bg[0];
        const float bd0 = bd[0];
        #pragma unroll
        for (int rr = 0; rr < 8; ++rr) {
            const int row = wid * 8 + rr;
            const float* er = emb + row * HID;
            float ag = 0.f, ad = 0.f;
            #pragma unroll
            for (int k = 0; k < 8; ++k) {
                float e = er[lane + 32 * k];
                ag += e * Wg[lane + 32 * k];
                ad += e * Wd[lane + 32 * k];
            }
            #pragma unroll
            for (int off = 16; off > 0; off >>= 1) {
                ag += __shfl_xor_sync(0xffffffffu, ag, off);
                ad += __shfl_xor_sync(0xffffffffu, ad, off);
            }
            if (lane == 0) {
                s_dem[row] = ad + bd0;
                float x = ag + bg0;
                float ws = 1.f / (1.f + expf(-x));
                if (ws >= 0.4f) atomicOr(&s_am[row >> 5], 1u << (row & 31));
            }
        }
    }
    s_elv[tid] = emb[lv * HID + tid];
    __syncthreads();

    // ranks by ascending dem (tie: lower vid)
    if (tid < VOCAB) {
        float dv = s_dem[tid];
        int rank = 0;
        #pragma unroll 8
        for (int u = 0; u < VOCAB; ++u) {
            float du = s_dem[u];
            if (du < dv || (du == dv && u < tid)) rank++;
        }
        s_rankv[tid] = rank;
        s_vid[rank] = tid;
    }
    __syncthreads();

    const u64 act = (u64)s_am[0] | ((u64)s_am[1] << 32);

    // ---- pass 1: active flags, per-chunk counts, rank bytes ----
    #pragma unroll
    for (int it = 0; it < 8; ++it) {
        const int chunk = wid * 8 + it;
        const int t = chunk * 32 + lane;
        bool a = false; int rk = 0;
        if (t < TLOOP) {
            int v = sb[t];
            a = ((act >> v) & 1ull) != 0ull;
            rk = s_rankv[v];
        }
        unsigned ball = __ballot_sync(0xffffffffu, a);
        s_tok[chunk * 32 + lane] = a ? (uint8_t)rk : (uint8_t)0xFF;
        if (lane == 0) s_ccnt[chunk] = __popc(ball);
    }
    __syncthreads();

    if (tid == 0) {
        int acc = 0;
        for (int c = 0; c < 64; ++c) { s_cpre[c] = acc; acc += s_ccnt[c]; }
        s_m = acc;
    }
    __syncthreads();

    const int m = s_m;
    const int ne = (m > FAST) ? (m - FAST) : 0;
    const int k1 = ne;
    const int k2 = (ne > SLOW) ? (ne - SLOW) : 0;
    const int scnt = (ne < SLOW) ? ne : SLOW;

    // ---- pass 2: histograms with positional cutoffs ----
    #pragma unroll
    for (int it = 0; it < 8; ++it) {
        const int chunk = wid * 8 + it;
        const int pos = chunk * 32 + lane;
        uint8_t tb = s_tok[pos];
        bool a = (tb != (uint8_t)0xFF);
        unsigned ball = __ballot_sync(0xffffffffu, a);
        if (a) {
            int yi = s_cpre[chunk] + __popc(ball & ((1u << lane) - 1u)) + 1;
            atomicAdd(&s_ha[tb], 1);
            if (yi >= m - 256 && yi <= m - 1) atomicAdd(&s_ht[tb], 1);
            if (yi == m) s_mrank = (int)tb;
        }
    }
    __syncthreads();

    const int mrank = s_mrank;
    if (tid < VOCAB) {
        int h1 = s_ha[tid] - (tid == mrank ? 1 : 0);
        s_h1[tid] = h1;
        s_h2[tid] = h1 - s_ht[tid];
    }
    __syncthreads();

    // ---- closed-form eviction multisets via prefix cutoffs ----
    int ct = 0;
    if (tid < VOCAB) {
        int cum1 = 0, cum2 = 0;
        for (int u = 0; u < tid; ++u) { cum1 += s_h1[u]; cum2 += s_h2[u]; }
        const int h1 = s_h1[tid], h2 = s_h2[tid];
        int e1 = k1 - cum1; e1 = e1 < 0 ? 0 : e1; e1 = e1 > h1 ? h1 : e1;
        int e2 = k2 - cum2; e2 = e2 < 0 ? 0 : e2; e2 = e2 > h2 ? h2 : e2;
        const int slow_h = e1 - e2;                    // last <=256 demotions
        const int fast_c = h1 - e1 + (tid == mrank ? 1 : 0);
        ct = fast_c + slow_h;
    }

    // ---- q = emb[lv] @ Wq + bq  (256 threads, coalesced columns) ----
    {
        float acc = bq[tid];
        #pragma unroll 8
        for (int h = 0; h < HID; ++h) acc += s_elv[h] * Wq[h * HID + tid];
        s_q[tid] = acc;
    }
    __syncthreads();

    // ---- p[rank] = emb[vid(rank)] . q  (8 warps x 8 ranks) ----
    #pragma unroll
    for (int rr = 0; rr < 8; ++rr) {
        const int r = wid * 8 + rr;
        const float* er = emb + s_vid[r] * HID;
        float acc = 0.f;
        #pragma unroll
        for (int k = 0; k < 8; ++k)
            acc += er[lane + 32 * k] * s_q[lane + 32 * k];
        #pragma unroll
        for (int off = 16; off > 0; off >>= 1)
            acc += __shfl_xor_sync(0xffffffffu, acc, off);
        if (lane == 0) s_p[r] = acc;
    }
    __syncthreads();

    // ---- softmax over ranks weighted by counts ----
    float v = (tid < VOCAB && ct > 0) ? s_p[tid] : -3.402823466e38f;
    #pragma unroll
    for (int off = 16; off > 0; off >>= 1)
        v = fmaxf(v, __shfl_xor_sync(0xffffffffu, v, off));
    if (lane == 0) s_r8[wid] = v;
    __syncthreads();
    float mx = s_r8[0];
    #pragma unroll
    for (int w = 1; w < 8; ++w) mx = fmaxf(mx, s_r8[w]);
    __syncthreads();

    float e = (tid < VOCAB && ct > 0) ? (float)ct * expf(s_p[tid] - mx) : 0.f;
    float sm = e;
    #pragma unroll
    for (int off = 16; off > 0; off >>= 1)
        sm += __shfl_xor_sync(0xffffffffu, sm, off);
    if (lane == 0) s_r8[wid] = sm;
    __syncthreads();
    float tot = 0.f;
    #pragma unroll
    for (int w = 0; w < 8; ++w) tot += s_r8[w];
    const float inv = (tot > 0.f) ? (1.f / tot) : 0.f;
    if (tid < VOCAB) s_w[tid] = e * inv;
    __syncthreads();

    // ---- ctx[h] = sum_r w[r] * emb[vid[r]][h] ----
    {
        float c = 0.f;
        #pragma unroll 8
        for (int r = 0; r < VOCAB; ++r)
            c += s_w[r] * emb[s_vid[r] * HID + tid];
        s_ctx[tid] = c;
    }
    __syncthreads();

    // ---- logits[j] = bo[j] + ctx . Wo[:,j]  (4 h-quarters x 64 j) ----
    {
        const int j = tid & 63;
        const int qd = tid >> 6;
        float acc = 0.f;
        #pragma unroll 8
        for (int k = 0; k < 64; ++k) {
            const int h = qd * 64 + k;
            acc += s_ctx[h] * Wo[h * VOCAB + j];
        }
        s_half[tid] = acc;
    }
    __syncthreads();
    if (tid < VOCAB)
        out[b * VOCAB + tid] = bo[tid] + s_half[tid] + s_half[tid + 64] +
                               s_half[tid + 128] + s_half[tid + 192];

    // slow_mask: slow slots fill sequentially
    for (int j = tid; j < SLOW; j += 256)
        out[BATCH * VOCAB + b * SLOW + j] = (j < scnt) ? 1.f : 0.f;
}

extern "C" void kernel_launch(void* const* d_in, const int* in_sizes, int n_in,
                              void* d_out, int out_size) {
    const int*   seq = (const int*)d_in[0];
    const float* emb = (const float*)d_in[1];
    const float* Wg  = (const float*)d_in[2];
    const float* bg  = (const float*)d_in[3];
    const float* Wd  = (const float*)d_in[4];
    const float* bd  = (const float*)d_in[5];
    const float* Wq  = (const float*)d_in[6];
    const float* bq  = (const float*)d_in[7];
    const float* Wo  = (const float*)d_in[8];
    const float* bo  = (const float*)d_in[9];
    float* out = (float*)d_out;

    fused_kernel<<<BATCH, 256>>>(seq, emb, Wg, bg, Wd, bd, Wq, bq, Wo, bo, out);
}